// round 9
// baseline (speedup 1.0000x reference)
#include <cuda_runtime.h>

#define B_    4
#define D_    96
#define N_    512
#define ATTN_ 256

// Scratch for projections (device globals: no allocation in kernel_launch)
__device__ float g_G1[B_ * N_ * ATTN_];   // [b][n][a]
__device__ float g_G2[B_ * N_ * ATTN_];   // [b][m][a]  (bg folded in)

__device__ __forceinline__ float fast_tanh(float x) {
    float y;
    asm("tanh.approx.f32 %0, %1;" : "=f"(y) : "f"(x));
    return y;
}

// ---------------------------------------------------------------------------
// Kernel 1: projections. grid = B*N/16 = 128 blocks, 256 threads (one per a).
// Each block handles 16 n-rows; thread a computes 16 dot products over D=96
// for both Wg1 and Wg2, reusing the weight element across the 16 rows.
// ---------------------------------------------------------------------------
__global__ __launch_bounds__(256) void proj_kernel(
        const float* __restrict__ x,
        const float* __restrict__ Wg1,
        const float* __restrict__ Wg2,
        const float* __restrict__ bg) {
    __shared__ float xs[16 * 96];  // xs[j*96 + d] = x[b, d, n0+j]

    int t  = blockIdx.x;
    int b  = t >> 5;           // 32 tiles of 16 per batch
    int n0 = (t & 31) << 4;

    const float* xb = x + b * D_ * N_;
    for (int idx = threadIdx.x; idx < 16 * 96; idx += 256) {
        int d = idx >> 4, j = idx & 15;
        xs[j * 96 + d] = xb[d * N_ + n0 + j];
    }
    __syncthreads();

    int a = threadIdx.x;
    float acc1[16], acc2[16];
#pragma unroll
    for (int j = 0; j < 16; j++) { acc1[j] = 0.f; acc2[j] = 0.f; }

    const float* w1p = Wg1 + a * D_;
    const float* w2p = Wg2 + a * D_;
#pragma unroll 4
    for (int d = 0; d < D_; d++) {
        float w1 = __ldg(w1p + d);
        float w2 = __ldg(w2p + d);
#pragma unroll
        for (int j = 0; j < 16; j++) {
            float xv = xs[j * 96 + d];
            acc1[j] = fmaf(xv, w1, acc1[j]);
            acc2[j] = fmaf(xv, w2, acc2[j]);
        }
    }

    float bgv = bg[a];
#pragma unroll
    for (int j = 0; j < 16; j++) {
        int row = b * N_ + n0 + j;
        g_G1[row * ATTN_ + a] = acc1[j];
        g_G2[row * ATTN_ + a] = acc2[j] + bgv;
    }
}

// ---------------------------------------------------------------------------
// Kernel 2: fused pairwise tanh + sigmoid + output matmul.
// grid = B * (N/8) = 256 blocks, 256 threads (8 warps).
// warp w <-> n = n0+w ; lane l <-> m = m0+l within a 32-wide m-tile.
// Epilogue: thread (w,l) accumulates out[n0+w][l], [l+32], [l+64].
// ---------------------------------------------------------------------------
#define NT 8
#define MT 32

// float offsets into dynamic smem
#define OFF_G1   0                      // 8*256  = 2048
#define OFF_WS   2048                   // 256
#define OFF_ATT  2304                   // 8*33   = 264
#define OFF_G2   2568                   // 256*33 = 8448
#define OFF_XS   11016                  // 32*97  = 3104
#define SMEM_FLOATS 14120               // 56480 bytes

__global__ __launch_bounds__(256, 2) void attn_kernel(
        const float* __restrict__ x,
        const float* __restrict__ Wa_w,
        const float* __restrict__ Wa_b,
        const float* __restrict__ ba,
        float* __restrict__ out) {
    extern __shared__ float sm[];
    float* G1s   = sm + OFF_G1;    // [n][a]
    float* ws    = sm + OFF_WS;    // [a]
    float* att_s = sm + OFF_ATT;   // [n][33]
    float* G2s   = sm + OFF_G2;    // [a][33] (m in low index, pad 33)
    float* xs    = sm + OFF_XS;    // [m][97] (d in low index, pad 97)

    int blk = blockIdx.x;
    int b   = blk >> 6;            // 64 n-tiles per batch
    int n0  = (blk & 63) << 3;
    int tid = threadIdx.x;
    int w   = tid >> 5, l = tid & 31;

    // Load G1 tile (coalesced over a) + attention weights
    for (int idx = tid; idx < NT * ATTN_; idx += 256)
        G1s[idx] = g_G1[(b * N_ + n0) * ATTN_ + idx];
    ws[tid] = Wa_w[tid];
    float bias = Wa_b[0] + ba[0];

    const float* xb = x + b * D_ * N_;
    float o0 = 0.f, o1 = 0.f, o2 = 0.f;

    for (int mt = 0; mt < N_ / MT; mt++) {
        int m0 = mt * MT;
        __syncthreads();  // previous tile's reads of G2s/xs (and G1s/ws load) done

        // G2 tile, transposed into [a][m] with pad 33 (store: stride-33, CF;
        // read: stride-1 over lanes, CF). Loads coalesced over a.
        const float* g2p = g_G2 + (b * N_ + m0) * ATTN_;
#pragma unroll 8
        for (int k = 0; k < MT; k++)
            G2s[tid * 33 + k] = g2p[k * ATTN_ + tid];

        // x tile [m][d] pad 97: global loads coalesced over m, smem stores CF.
        for (int idx = tid; idx < MT * D_; idx += 256) {
            int m = idx & 31, d = idx >> 5;
            xs[m * 97 + d] = xb[d * N_ + m0 + m];
        }
        __syncthreads();

        // Hot loop: 256 a per (n,m) pair. 4 accumulators for ILP;
        // G1/ws broadcast via LDS.128, G2 lane-parallel conflict-free.
        const float* g1p = G1s + w * ATTN_;
        float a0 = 0.f, a1 = 0.f, a2 = 0.f, a3 = 0.f;
#pragma unroll 4
        for (int a = 0; a < ATTN_; a += 4) {
            float4 g1 = *reinterpret_cast<const float4*>(g1p + a);
            float4 wv = *reinterpret_cast<const float4*>(ws + a);
            float s0 = g1.x + G2s[(a + 0) * 33 + l];
            float s1 = g1.y + G2s[(a + 1) * 33 + l];
            float s2 = g1.z + G2s[(a + 2) * 33 + l];
            float s3 = g1.w + G2s[(a + 3) * 33 + l];
            a0 = fmaf(fast_tanh(s0), wv.x, a0);
            a1 = fmaf(fast_tanh(s1), wv.y, a1);
            a2 = fmaf(fast_tanh(s2), wv.z, a2);
            a3 = fmaf(fast_tanh(s3), wv.w, a3);
        }
        float z   = (a0 + a1) + (a2 + a3) + bias;
        float att = 1.0f / (1.0f + __expf(-z));
        att_s[w * 33 + l] = att;
        __syncthreads();

        // Fused epilogue: out[n][d] += att[n][m] * x[b][d][m] over this m-tile.
        const float* ar = att_s + w * 33;
#pragma unroll 8
        for (int mm = 0; mm < MT; mm++) {
            float av = ar[mm];                      // warp broadcast
            o0 = fmaf(av, xs[mm * 97 + l],      o0);
            o1 = fmaf(av, xs[mm * 97 + l + 32], o1);
            o2 = fmaf(av, xs[mm * 97 + l + 64], o2);
        }
    }

    float* op = out + (b * N_ + n0 + w) * D_;
    op[l]      = o0;
    op[l + 32] = o1;
    op[l + 64] = o2;
}

// ---------------------------------------------------------------------------
extern "C" void kernel_launch(void* const* d_in, const int* in_sizes, int n_in,
                              void* d_out, int out_size) {
    const float* x    = (const float*)d_in[0];
    const float* Wg1  = (const float*)d_in[1];
    const float* Wg2  = (const float*)d_in[2];
    const float* bg   = (const float*)d_in[3];
    const float* Wa_w = (const float*)d_in[4];
    const float* Wa_b = (const float*)d_in[5];
    const float* ba   = (const float*)d_in[6];
    float* out = (float*)d_out;

    proj_kernel<<<(B_ * N_) / 16, 256>>>(x, Wg1, Wg2, bg);

    int smem_bytes = SMEM_FLOATS * (int)sizeof(float);  // 56480
    cudaFuncSetAttribute(attn_kernel,
                         cudaFuncAttributeMaxDynamicSharedMemorySize, smem_bytes);
    attn_kernel<<<B_ * (N_ / NT), 256, smem_bytes>>>(x, Wa_w, Wa_b, ba, out);
}

// round 10
// speedup vs baseline: 1.8507x; 1.8507x over previous
#include <cuda_runtime.h>

#define B_    4
#define D_    96
#define N_    512
#define ATTN_ 256

// Scratch for projections (device globals: no allocation in kernel_launch)
__device__ float g_G1[B_ * N_ * ATTN_];   // [b][n][a]
__device__ float g_G2[B_ * N_ * ATTN_];   // [b][m][a]  (bg folded in)

__device__ __forceinline__ float fast_tanh(float x) {
    float y;
    asm("tanh.approx.f32 %0, %1;" : "=f"(y) : "f"(x));
    return y;
}

// ---------------------------------------------------------------------------
// Kernel 1: projections. grid = B*N/8 = 256 blocks, 256 threads (one per a).
// Both weight matrices staged in smem (197KB) with COALESCED float4 global
// loads; per-thread weight reads hit smem conflict-free via pad-97 rows.
// Each thread computes 8 rows x 2 projections, x-tile broadcast via LDS.128.
// ---------------------------------------------------------------------------
#define PR 8  // n-rows per proj block

__global__ __launch_bounds__(256) void proj_kernel(
        const float* __restrict__ x,
        const float* __restrict__ Wg1,
        const float* __restrict__ Wg2,
        const float* __restrict__ bg) {
    extern __shared__ float psm[];
    float* W1s = psm;                     // [256][97]
    float* W2s = psm + 256 * 97;          // [256][97]
    float* xs  = psm + 2 * 256 * 97;      // [96][8]: xs[d*8+j] = x[b,d,n0+j]

    int blk = blockIdx.x;
    int b   = blk >> 6;
    int n0  = (blk & 63) << 3;
    int tid = threadIdx.x;

    // Weights: coalesced float4 loads (96 floats = 24 float4 per a-row).
    for (int idx = tid; idx < 256 * 24; idx += 256) {
        int a = idx / 24;
        int c = idx - a * 24;
        float4 v1 = reinterpret_cast<const float4*>(Wg1)[idx];
        float4 v2 = reinterpret_cast<const float4*>(Wg2)[idx];
        float* d1 = W1s + a * 97 + c * 4;
        float* d2 = W2s + a * 97 + c * 4;
        d1[0] = v1.x; d1[1] = v1.y; d1[2] = v1.z; d1[3] = v1.w;
        d2[0] = v2.x; d2[1] = v2.y; d2[2] = v2.z; d2[3] = v2.w;
    }

    const float* xb = x + b * D_ * N_;
    for (int idx = tid; idx < D_ * PR; idx += 256) {
        int d = idx >> 3, j = idx & 7;
        xs[idx] = xb[d * N_ + n0 + j];
    }
    __syncthreads();

    int a = tid;
    float acc1[PR], acc2[PR];
#pragma unroll
    for (int j = 0; j < PR; j++) { acc1[j] = 0.f; acc2[j] = 0.f; }

    const float* w1 = W1s + a * 97;   // bank (a+d)%32: conflict-free
    const float* w2 = W2s + a * 97;
#pragma unroll 4
    for (int d = 0; d < D_; d++) {
        float wa = w1[d];
        float wb = w2[d];
        float4 x0 = *reinterpret_cast<const float4*>(xs + d * 8);      // broadcast
        float4 x1 = *reinterpret_cast<const float4*>(xs + d * 8 + 4);  // broadcast
        acc1[0] = fmaf(x0.x, wa, acc1[0]); acc2[0] = fmaf(x0.x, wb, acc2[0]);
        acc1[1] = fmaf(x0.y, wa, acc1[1]); acc2[1] = fmaf(x0.y, wb, acc2[1]);
        acc1[2] = fmaf(x0.z, wa, acc1[2]); acc2[2] = fmaf(x0.z, wb, acc2[2]);
        acc1[3] = fmaf(x0.w, wa, acc1[3]); acc2[3] = fmaf(x0.w, wb, acc2[3]);
        acc1[4] = fmaf(x1.x, wa, acc1[4]); acc2[4] = fmaf(x1.x, wb, acc2[4]);
        acc1[5] = fmaf(x1.y, wa, acc1[5]); acc2[5] = fmaf(x1.y, wb, acc2[5]);
        acc1[6] = fmaf(x1.z, wa, acc1[6]); acc2[6] = fmaf(x1.z, wb, acc2[6]);
        acc1[7] = fmaf(x1.w, wa, acc1[7]); acc2[7] = fmaf(x1.w, wb, acc2[7]);
    }

    float bgv = bg[a];
#pragma unroll
    for (int j = 0; j < PR; j++) {
        int row = b * N_ + n0 + j;
        g_G1[row * ATTN_ + a] = acc1[j];
        g_G2[row * ATTN_ + a] = acc2[j] + bgv;
    }
}

// ---------------------------------------------------------------------------
// Kernel 2: fused pairwise tanh + sigmoid + output matmul, SPLIT over m.
// grid = B * (N/8) * 2 = 512 blocks (all co-resident at 4 blocks/SM),
// 256 threads (8 warps). warp w <-> n = n0+w; lane l <-> m = m0+l.
// Each block covers one m-half (256 m's, 8 tiles of 32); partial outputs
// combined with atomicAdd into a pre-zeroed out buffer.
// G2 tile kept in NATURAL [m][a] layout, rows padded to 260 floats so each
// lane fetches its 4 G2 values with a single LDS.128 (exact 4-phase floor).
// ---------------------------------------------------------------------------
#define NT 8
#define MT 32

// float offsets into dynamic smem
#define OFF_G1   0                      // 8*256  = 2048
#define OFF_WS   2048                   // 256
#define OFF_ATT  2304                   // 8*33   = 264
#define OFF_G2   2568                   // 32*260 = 8320
#define OFF_XS   10888                  // 32*97  = 3104
#define SMEM_FLOATS 13992               // 55968 bytes -> 4 blocks/SM

__global__ __launch_bounds__(256, 4) void attn_kernel(
        const float* __restrict__ x,
        const float* __restrict__ Wa_w,
        const float* __restrict__ Wa_b,
        const float* __restrict__ ba,
        float* __restrict__ out) {
    extern __shared__ float sm[];
    float* G1s   = sm + OFF_G1;    // [n][a]
    float* ws    = sm + OFF_WS;    // [a]
    float* att_s = sm + OFF_ATT;   // [n][33]
    float* G2n   = sm + OFF_G2;    // [m][260] natural layout, pad 260
    float* xs    = sm + OFF_XS;    // [m][97]

    int blk  = blockIdx.x;         // 512 = B * 64 * 2
    int b    = blk >> 7;
    int r    = blk & 127;
    int nt   = r >> 1;
    int half = r & 1;
    int n0   = nt << 3;
    int mbase = half << 8;         // 0 or 256
    int tid  = threadIdx.x;
    int w    = tid >> 5, l = tid & 31;

    // G1 tile (coalesced over a) + attention weights
    for (int idx = tid; idx < NT * ATTN_; idx += 256)
        G1s[idx] = g_G1[(b * N_ + n0) * ATTN_ + idx];
    ws[tid] = Wa_w[tid];
    float bias = Wa_b[0] + ba[0];

    const float* xb = x + b * D_ * N_;
    float o0 = 0.f, o1 = 0.f, o2 = 0.f;

    for (int mt = 0; mt < 8; mt++) {
        int m0 = mbase + mt * MT;
        __syncthreads();  // prev tile's reads done (and initial G1/ws load)

        // G2 tile, natural [m][a] pad-260. Global reads fully coalesced
        // (g2p[idx] is contiguous); smem stores conflict-free.
        const float* g2p = g_G2 + (b * N_ + m0) * ATTN_;
        for (int idx = tid; idx < MT * ATTN_; idx += 256) {
            int m = idx >> 8, a = idx & 255;
            G2n[m * 260 + a] = g2p[idx];
        }
        // x tile [m][97]: global coalesced over m, smem stores conflict-free.
        for (int idx = tid; idx < MT * D_; idx += 256) {
            int m = idx & 31, d = idx >> 5;
            xs[m * 97 + d] = xb[d * N_ + m0 + m];
        }
        __syncthreads();

        // Hot loop: 15 instr / 4 tanh. G1/ws broadcast LDS.128,
        // G2 one LDS.128 per lane (4-phase floor), 4 accumulators for ILP.
        const float* g1p = G1s + w * ATTN_;
        const float* g2l = G2n + l * 260;
        float a0 = 0.f, a1 = 0.f, a2 = 0.f, a3 = 0.f;
#pragma unroll 4
        for (int a = 0; a < ATTN_; a += 4) {
            float4 g1 = *reinterpret_cast<const float4*>(g1p + a);
            float4 wv = *reinterpret_cast<const float4*>(ws + a);
            float4 g2 = *reinterpret_cast<const float4*>(g2l + a);
            a0 = fmaf(fast_tanh(g1.x + g2.x), wv.x, a0);
            a1 = fmaf(fast_tanh(g1.y + g2.y), wv.y, a1);
            a2 = fmaf(fast_tanh(g1.z + g2.z), wv.z, a2);
            a3 = fmaf(fast_tanh(g1.w + g2.w), wv.w, a3);
        }
        float z   = (a0 + a1) + (a2 + a3) + bias;
        float att = 1.0f / (1.0f + __expf(-z));
        att_s[w * 33 + l] = att;
        __syncthreads();

        // Fused epilogue: out[n][d] += att[n][m] * x[b][d][m] over this m-tile.
        const float* ar = att_s + w * 33;
#pragma unroll 8
        for (int mm = 0; mm < MT; mm += 4) {
            float av0 = ar[mm + 0];
            float av1 = ar[mm + 1];
            float av2 = ar[mm + 2];
            float av3 = ar[mm + 3];
            o0 = fmaf(av0, xs[(mm + 0) * 97 + l],      o0);
            o1 = fmaf(av0, xs[(mm + 0) * 97 + l + 32], o1);
            o2 = fmaf(av0, xs[(mm + 0) * 97 + l + 64], o2);
            o0 = fmaf(av1, xs[(mm + 1) * 97 + l],      o0);
            o1 = fmaf(av1, xs[(mm + 1) * 97 + l + 32], o1);
            o2 = fmaf(av1, xs[(mm + 1) * 97 + l + 64], o2);
            o0 = fmaf(av2, xs[(mm + 2) * 97 + l],      o0);
            o1 = fmaf(av2, xs[(mm + 2) * 97 + l + 32], o1);
            o2 = fmaf(av2, xs[(mm + 2) * 97 + l + 64], o2);
            o0 = fmaf(av3, xs[(mm + 3) * 97 + l],      o0);
            o1 = fmaf(av3, xs[(mm + 3) * 97 + l + 32], o1);
            o2 = fmaf(av3, xs[(mm + 3) * 97 + l + 64], o2);
        }
    }

    // Combine the two m-halves.
    float* op = out + (b * N_ + n0 + w) * D_;
    atomicAdd(op + l,      o0);
    atomicAdd(op + l + 32, o1);
    atomicAdd(op + l + 64, o2);
}

// ---------------------------------------------------------------------------
extern "C" void kernel_launch(void* const* d_in, const int* in_sizes, int n_in,
                              void* d_out, int out_size) {
    const float* x    = (const float*)d_in[0];
    const float* Wg1  = (const float*)d_in[1];
    const float* Wg2  = (const float*)d_in[2];
    const float* bg   = (const float*)d_in[3];
    const float* Wa_w = (const float*)d_in[4];
    const float* Wa_b = (const float*)d_in[5];
    const float* ba   = (const float*)d_in[6];
    float* out = (float*)d_out;

    // out receives atomicAdd partials from both m-halves: zero it first.
    cudaMemsetAsync(d_out, 0, (size_t)out_size * sizeof(float));

    int proj_smem = (2 * 256 * 97 + D_ * PR) * (int)sizeof(float);  // 201,728 B
    cudaFuncSetAttribute(proj_kernel,
                         cudaFuncAttributeMaxDynamicSharedMemorySize, proj_smem);
    proj_kernel<<<(B_ * N_) / PR, 256, proj_smem>>>(x, Wg1, Wg2, bg);

    int attn_smem = SMEM_FLOATS * (int)sizeof(float);  // 55,968 B
    cudaFuncSetAttribute(attn_kernel,
                         cudaFuncAttributeMaxDynamicSharedMemorySize, attn_smem);
    attn_kernel<<<B_ * (N_ / NT) * 2, 256, attn_smem>>>(x, Wa_w, Wa_b, ba, out);
}

// round 11
// speedup vs baseline: 2.0300x; 1.0969x over previous
#include <cuda_runtime.h>

#define B_    4
#define D_    96
#define N_    512
#define ATTN_ 256

// Scratch for projections (device globals: no allocation in kernel_launch)
__device__ float g_G1[B_ * N_ * ATTN_];   // [b][n][a]
__device__ float g_G2[B_ * N_ * ATTN_];   // [b][m][a]  (bg folded in)

__device__ __forceinline__ float fast_tanh(float x) {
    float y;
    asm("tanh.approx.f32 %0, %1;" : "=f"(y) : "f"(x));
    return y;
}

// ---------------------------------------------------------------------------
// Kernel 1: projections. grid = B*N/8 = 256 blocks, 256 threads (one per a).
// Both weight matrices staged in smem with COALESCED float4 global loads;
// per-thread weight reads hit smem conflict-free via pad-97 rows.
// ---------------------------------------------------------------------------
#define PR 8  // n-rows per proj block

__global__ __launch_bounds__(256) void proj_kernel(
        const float* __restrict__ x,
        const float* __restrict__ Wg1,
        const float* __restrict__ Wg2,
        const float* __restrict__ bg) {
    extern __shared__ float psm[];
    float* W1s = psm;                     // [256][97]
    float* W2s = psm + 256 * 97;          // [256][97]
    float* xs  = psm + 2 * 256 * 97;      // [96][8]: xs[d*8+j] = x[b,d,n0+j]

    int blk = blockIdx.x;
    int b   = blk >> 6;
    int n0  = (blk & 63) << 3;
    int tid = threadIdx.x;

    // Weights: coalesced float4 loads (96 floats = 24 float4 per a-row).
    for (int idx = tid; idx < 256 * 24; idx += 256) {
        int a = idx / 24;
        int c = idx - a * 24;
        float4 v1 = reinterpret_cast<const float4*>(Wg1)[idx];
        float4 v2 = reinterpret_cast<const float4*>(Wg2)[idx];
        float* d1 = W1s + a * 97 + c * 4;
        float* d2 = W2s + a * 97 + c * 4;
        d1[0] = v1.x; d1[1] = v1.y; d1[2] = v1.z; d1[3] = v1.w;
        d2[0] = v2.x; d2[1] = v2.y; d2[2] = v2.z; d2[3] = v2.w;
    }

    const float* xb = x + b * D_ * N_;
    for (int idx = tid; idx < D_ * PR; idx += 256) {
        int d = idx >> 3, j = idx & 7;
        xs[idx] = xb[d * N_ + n0 + j];
    }
    __syncthreads();

    int a = tid;
    float acc1[PR], acc2[PR];
#pragma unroll
    for (int j = 0; j < PR; j++) { acc1[j] = 0.f; acc2[j] = 0.f; }

    const float* w1 = W1s + a * 97;   // bank (a+d)%32: conflict-free
    const float* w2 = W2s + a * 97;
#pragma unroll 4
    for (int d = 0; d < D_; d++) {
        float wa = w1[d];
        float wb = w2[d];
        float4 x0 = *reinterpret_cast<const float4*>(xs + d * 8);      // broadcast
        float4 x1 = *reinterpret_cast<const float4*>(xs + d * 8 + 4);  // broadcast
        acc1[0] = fmaf(x0.x, wa, acc1[0]); acc2[0] = fmaf(x0.x, wb, acc2[0]);
        acc1[1] = fmaf(x0.y, wa, acc1[1]); acc2[1] = fmaf(x0.y, wb, acc2[1]);
        acc1[2] = fmaf(x0.z, wa, acc1[2]); acc2[2] = fmaf(x0.z, wb, acc2[2]);
        acc1[3] = fmaf(x0.w, wa, acc1[3]); acc2[3] = fmaf(x0.w, wb, acc2[3]);
        acc1[4] = fmaf(x1.x, wa, acc1[4]); acc2[4] = fmaf(x1.x, wb, acc2[4]);
        acc1[5] = fmaf(x1.y, wa, acc1[5]); acc2[5] = fmaf(x1.y, wb, acc2[5]);
        acc1[6] = fmaf(x1.z, wa, acc1[6]); acc2[6] = fmaf(x1.z, wb, acc2[6]);
        acc1[7] = fmaf(x1.w, wa, acc1[7]); acc2[7] = fmaf(x1.w, wb, acc2[7]);
    }

    float bgv = bg[a];
#pragma unroll
    for (int j = 0; j < PR; j++) {
        int row = b * N_ + n0 + j;
        g_G1[row * ATTN_ + a] = acc1[j];
        g_G2[row * ATTN_ + a] = acc2[j] + bgv;
    }
}

// ---------------------------------------------------------------------------
// Kernel 2: fused pairwise tanh + sigmoid + output matmul, SPLIT over m.
// grid = B * (N/8) * 2 = 512 blocks (4 blocks/SM), 256 threads (8 warps).
//
// Warp w -> (npair p = w>>1, m-half msub = w&1). Lane l -> n = n0+2p+(l>>4),
// m-in-tile ml = msub*16 + (l&15). Hot loop: 5 wavefronts / 4-a step
// (2 g1 broadcasts + 1 ws broadcast + 2 for the 16-m deduped g2 LDS.128).
// att_s rows are produced and consumed by the SAME warp -> __syncwarp only.
// Epilogue: thread accumulates BOTH n of its pair x 3 d (xs reuse across n):
// 5 wf / 6 FMA. Partials combined by atomicAdd into pre-zeroed out.
// ---------------------------------------------------------------------------
#define NT 8
#define MT 32

// float offsets into dynamic smem
#define OFF_G1   0                      // 8*256  = 2048
#define OFF_WS   2048                   // 256
#define OFF_ATT  2304                   // 8*33   = 264
#define OFF_G2   2568                   // 32*260 = 8320
#define OFF_XS   10888                  // 32*97  = 3104
#define SMEM_FLOATS 13992               // 55968 bytes -> 4 blocks/SM

__global__ __launch_bounds__(256, 4) void attn_kernel(
        const float* __restrict__ x,
        const float* __restrict__ Wa_w,
        const float* __restrict__ Wa_b,
        const float* __restrict__ ba,
        float* __restrict__ out) {
    extern __shared__ float sm[];
    float* G1s   = sm + OFF_G1;    // [n][a]
    float* ws    = sm + OFF_WS;    // [a]
    float* att_s = sm + OFF_ATT;   // [n][33]
    float* G2n   = sm + OFF_G2;    // [m][260] natural layout, pad 260
    float* xs    = sm + OFF_XS;    // [m][97]

    int blk  = blockIdx.x;         // 512 = B * 64 * 2
    int b    = blk >> 7;
    int r    = blk & 127;
    int n0   = (r >> 1) << 3;
    int mbase = (r & 1) << 8;      // 0 or 256
    int tid  = threadIdx.x;
    int w    = tid >> 5, l = tid & 31;
    int p    = w >> 1;             // npair index 0..3
    int msub = w & 1;              // m half of each 32-tile
    int lh   = l >> 4;             // n within pair (0/1)
    int ml   = (msub << 4) + (l & 15);  // m within tile 0..31

    // G1 tile + attention weights (float4 coalesced; G1s row = 256 floats, no pad)
    {
        const float4* g1g = reinterpret_cast<const float4*>(
                                g_G1 + (b * N_ + n0) * ATTN_);
        float4* g1d = reinterpret_cast<float4*>(G1s);
        for (int idx = tid; idx < NT * ATTN_ / 4; idx += 256)
            g1d[idx] = g1g[idx];
    }
    ws[tid] = Wa_w[tid];
    float bias = Wa_b[0] + ba[0];

    const float* xb = x + b * D_ * N_;
    // Per-thread partial outputs: rows n=2p and n=2p+1, d = l, l+32, l+64.
    float o00 = 0.f, o01 = 0.f, o02 = 0.f;
    float o10 = 0.f, o11 = 0.f, o12 = 0.f;

    const float* g1p = G1s + ((p << 1) + lh) * ATTN_;
    const float* g2l = G2n + ml * 260;
    const float* ar0 = att_s + (p << 1) * 33;

    for (int mt = 0; mt < 8; mt++) {
        int m0 = mbase + mt * MT;
        __syncthreads();  // prev tile's epilogue xs/G2n reads done

        // G2 tile, natural [m][a] pad-260 (260%4==0 -> float4 rows).
        {
            const float4* g2g = reinterpret_cast<const float4*>(
                                    g_G2 + (b * N_ + m0) * ATTN_);
            for (int idx = tid; idx < MT * ATTN_ / 4; idx += 256) {
                int m = idx >> 6, c = idx & 63;      // 64 float4 per m-row
                *reinterpret_cast<float4*>(G2n + m * 260 + c * 4) = g2g[idx];
            }
        }
        // x tile [m][97]: global coalesced over m, smem stores conflict-free.
        for (int idx = tid; idx < MT * D_; idx += 256) {
            int m = idx & 31, d = idx >> 5;
            xs[m * 97 + d] = xb[d * N_ + m0 + m];
        }
        __syncthreads();

        // Hot loop: per 4-a step 15 instr / 5 wavefronts.
        float a0 = 0.f, a1 = 0.f, a2 = 0.f, a3 = 0.f;
#pragma unroll 2
        for (int a = 0; a < ATTN_; a += 4) {
            float4 g1 = *reinterpret_cast<const float4*>(g1p + a);
            float4 wv = *reinterpret_cast<const float4*>(ws + a);
            float4 g2 = *reinterpret_cast<const float4*>(g2l + a);
            a0 = fmaf(fast_tanh(g1.x + g2.x), wv.x, a0);
            a1 = fmaf(fast_tanh(g1.y + g2.y), wv.y, a1);
            a2 = fmaf(fast_tanh(g1.z + g2.z), wv.z, a2);
            a3 = fmaf(fast_tanh(g1.w + g2.w), wv.w, a3);
        }
        float z   = (a0 + a1) + (a2 + a3) + bias;
        float att = 1.0f / (1.0f + __expf(-z));
        att_s[((p << 1) + lh) * 33 + ml] = att;
        __syncwarp();   // producer == consumer warp for these att_s entries

        // Epilogue: both n of the pair share each xs load. 5 wf / 6 FMA.
#pragma unroll 4
        for (int mm = 0; mm < 16; mm++) {
            int mli = (msub << 4) + mm;
            float av0 = ar0[mli];            // broadcast
            float av1 = ar0[33 + mli];       // broadcast
            const float* xr = xs + mli * 97;
            float x0 = xr[l];
            float x1 = xr[l + 32];
            float x2 = xr[l + 64];
            o00 = fmaf(av0, x0, o00);
            o01 = fmaf(av0, x1, o01);
            o02 = fmaf(av0, x2, o02);
            o10 = fmaf(av1, x0, o10);
            o11 = fmaf(av1, x1, o11);
            o12 = fmaf(av1, x2, o12);
        }
    }

    // Combine m-halves (and the msub warp pair) into pre-zeroed out.
    float* op0 = out + (b * N_ + n0 + (p << 1)) * D_;
    float* op1 = op0 + D_;
    atomicAdd(op0 + l,      o00);
    atomicAdd(op0 + l + 32, o01);
    atomicAdd(op0 + l + 64, o02);
    atomicAdd(op1 + l,      o10);
    atomicAdd(op1 + l + 32, o11);
    atomicAdd(op1 + l + 64, o12);
}

// ---------------------------------------------------------------------------
extern "C" void kernel_launch(void* const* d_in, const int* in_sizes, int n_in,
                              void* d_out, int out_size) {
    const float* x    = (const float*)d_in[0];
    const float* Wg1  = (const float*)d_in[1];
    const float* Wg2  = (const float*)d_in[2];
    const float* bg   = (const float*)d_in[3];
    const float* Wa_w = (const float*)d_in[4];
    const float* Wa_b = (const float*)d_in[5];
    const float* ba   = (const float*)d_in[6];
    float* out = (float*)d_out;

    // out receives atomicAdd partials: zero it first.
    cudaMemsetAsync(d_out, 0, (size_t)out_size * sizeof(float));

    int proj_smem = (2 * 256 * 97 + D_ * PR) * (int)sizeof(float);
    cudaFuncSetAttribute(proj_kernel,
                         cudaFuncAttributeMaxDynamicSharedMemorySize, proj_smem);
    proj_kernel<<<(B_ * N_) / PR, 256, proj_smem>>>(x, Wg1, Wg2, bg);

    int attn_smem = SMEM_FLOATS * (int)sizeof(float);  // 55,968 B
    cudaFuncSetAttribute(attn_kernel,
                         cudaFuncAttributeMaxDynamicSharedMemorySize, attn_smem);
    attn_kernel<<<B_ * (N_ / NT) * 2, 256, attn_smem>>>(x, Wa_w, Wa_b, ba, out);
}

// round 12
// speedup vs baseline: 2.1533x; 1.0608x over previous
#include <cuda_runtime.h>

#define B_    4
#define D_    96
#define N_    512
#define ATTN_ 256

// Scratch for projections (device globals: no allocation in kernel_launch)
__device__ float g_G1[B_ * N_ * ATTN_];   // [b][n][a]
__device__ float g_G2[B_ * N_ * ATTN_];   // [b][m][a]  (bg folded in)

// Attention projection weights, copied in at launch (async D2D memcpy).
// Uniform-address reads -> const/uniform port, ZERO smem crossbar traffic.
__constant__ float c_ws[ATTN_];

__device__ __forceinline__ float fast_tanh(float x) {
    float y;
    asm("tanh.approx.f32 %0, %1;" : "=f"(y) : "f"(x));
    return y;
}

// ---------------------------------------------------------------------------
// Kernel 1: projections. grid = B*N/8 = 256 blocks, 256 threads (one per a).
// ---------------------------------------------------------------------------
#define PR 8  // n-rows per proj block

__global__ __launch_bounds__(256) void proj_kernel(
        const float* __restrict__ x,
        const float* __restrict__ Wg1,
        const float* __restrict__ Wg2,
        const float* __restrict__ bg) {
    extern __shared__ float psm[];
    float* W1s = psm;                     // [256][97]
    float* W2s = psm + 256 * 97;          // [256][97]
    float* xs  = psm + 2 * 256 * 97;      // [96][8]

    int blk = blockIdx.x;
    int b   = blk >> 6;
    int n0  = (blk & 63) << 3;
    int tid = threadIdx.x;

    for (int idx = tid; idx < 256 * 24; idx += 256) {
        int a = idx / 24;
        int c = idx - a * 24;
        float4 v1 = reinterpret_cast<const float4*>(Wg1)[idx];
        float4 v2 = reinterpret_cast<const float4*>(Wg2)[idx];
        float* d1 = W1s + a * 97 + c * 4;
        float* d2 = W2s + a * 97 + c * 4;
        d1[0] = v1.x; d1[1] = v1.y; d1[2] = v1.z; d1[3] = v1.w;
        d2[0] = v2.x; d2[1] = v2.y; d2[2] = v2.z; d2[3] = v2.w;
    }

    const float* xb = x + b * D_ * N_;
    for (int idx = tid; idx < D_ * PR; idx += 256) {
        int d = idx >> 3, j = idx & 7;
        xs[idx] = xb[d * N_ + n0 + j];
    }
    __syncthreads();

    int a = tid;
    float acc1[PR], acc2[PR];
#pragma unroll
    for (int j = 0; j < PR; j++) { acc1[j] = 0.f; acc2[j] = 0.f; }

    const float* w1 = W1s + a * 97;
    const float* w2 = W2s + a * 97;
#pragma unroll 4
    for (int d = 0; d < D_; d++) {
        float wa = w1[d];
        float wb = w2[d];
        float4 x0 = *reinterpret_cast<const float4*>(xs + d * 8);
        float4 x1 = *reinterpret_cast<const float4*>(xs + d * 8 + 4);
        acc1[0] = fmaf(x0.x, wa, acc1[0]); acc2[0] = fmaf(x0.x, wb, acc2[0]);
        acc1[1] = fmaf(x0.y, wa, acc1[1]); acc2[1] = fmaf(x0.y, wb, acc2[1]);
        acc1[2] = fmaf(x0.z, wa, acc1[2]); acc2[2] = fmaf(x0.z, wb, acc2[2]);
        acc1[3] = fmaf(x0.w, wa, acc1[3]); acc2[3] = fmaf(x0.w, wb, acc2[3]);
        acc1[4] = fmaf(x1.x, wa, acc1[4]); acc2[4] = fmaf(x1.x, wb, acc2[4]);
        acc1[5] = fmaf(x1.y, wa, acc1[5]); acc2[5] = fmaf(x1.y, wb, acc2[5]);
        acc1[6] = fmaf(x1.z, wa, acc1[6]); acc2[6] = fmaf(x1.z, wb, acc2[6]);
        acc1[7] = fmaf(x1.w, wa, acc1[7]); acc2[7] = fmaf(x1.w, wb, acc2[7]);
    }

    float bgv = bg[a];
#pragma unroll
    for (int j = 0; j < PR; j++) {
        int row = b * N_ + n0 + j;
        g_G1[row * ATTN_ + a] = acc1[j];
        g_G2[row * ATTN_ + a] = acc2[j] + bgv;
    }
}

// ---------------------------------------------------------------------------
// Kernel 2: fused pairwise tanh + sigmoid + output matmul.
// grid = B * (N/8) * 2 = 512 blocks (4 blocks/SM, single wave), 256 threads.
//
// Warp w: n-pair p = w&3, a-half g = w>>2 (a in [128g, 128g+128)).
// Lane l <-> m (full 32-m tile). Hot loop computes BOTH n of the pair from
// one g2 quad: per 4-a step = 2 g1 broadcast LDS.128 (8 wf) + 1 g2 LDS.128
// (4 wf) + const-port ws = 12 wf / 256 tanh (was 12/128).
// a-half partials exchanged via zbuf; g=0 computes sigmoid; epilogue split
// 16 m per group with the paired 5wf/6FMA pattern.
// ---------------------------------------------------------------------------
#define NT 8
#define MT 32

// float offsets into dynamic smem
#define OFF_G1   0                      // 8*256  = 2048
#define OFF_ATT  2048                   // 8*33   = 264
#define OFF_ZB   2312                   // 8*32   = 256
#define OFF_G2   2568                   // 32*260 = 8320
#define OFF_XS   10888                  // 32*97  = 3104
#define SMEM_FLOATS 13992               // 55968 bytes -> 4 blocks/SM

__global__ __launch_bounds__(256, 4) void attn_kernel(
        const float* __restrict__ x,
        const float* __restrict__ Wa_b,
        const float* __restrict__ ba,
        float* __restrict__ out) {
    extern __shared__ float sm[];
    float* G1s   = sm + OFF_G1;    // [n][256]
    float* att_s = sm + OFF_ATT;   // [n][33]
    float* zbuf  = sm + OFF_ZB;    // [n][32] partial z from group 1
    float* G2n   = sm + OFF_G2;    // [m][260]
    float* xs    = sm + OFF_XS;    // [m][97]

    int blk  = blockIdx.x;         // 512 = B * 64 * 2
    int b    = blk >> 7;
    int r    = blk & 127;
    int n0   = (r >> 1) << 3;
    int mbase = (r & 1) << 8;
    int tid  = threadIdx.x;
    int w    = tid >> 5, l = tid & 31;
    int p    = w & 3;              // n-pair 0..3
    int g    = w >> 2;             // a-half 0/1
    int a0   = g << 7;

    // G1 tile (float4 coalesced)
    {
        const float4* g1g = reinterpret_cast<const float4*>(
                                g_G1 + (b * N_ + n0) * ATTN_);
        float4* g1d = reinterpret_cast<float4*>(G1s);
        for (int idx = tid; idx < NT * ATTN_ / 4; idx += 256)
            g1d[idx] = g1g[idx];
    }
    float bias = Wa_b[0] + ba[0];

    const float* xb = x + b * D_ * N_;
    float o00 = 0.f, o01 = 0.f, o02 = 0.f;
    float o10 = 0.f, o11 = 0.f, o12 = 0.f;

    const float* g1p0 = G1s + (p << 1) * ATTN_;
    const float* g1p1 = g1p0 + ATTN_;
    const float* g2l  = G2n + l * 260;
    const float* ar0  = att_s + (p << 1) * 33;

    for (int mt = 0; mt < 8; mt++) {
        int m0 = mbase + mt * MT;
        __syncthreads();  // A: prev tile's epilogue readers done

        // Stage G2 tile [m][260] and x tile [m][97]
        {
            const float4* g2g = reinterpret_cast<const float4*>(
                                    g_G2 + (b * N_ + m0) * ATTN_);
            for (int idx = tid; idx < MT * ATTN_ / 4; idx += 256) {
                int m = idx >> 6, c = idx & 63;
                *reinterpret_cast<float4*>(G2n + m * 260 + c * 4) = g2g[idx];
            }
        }
        for (int idx = tid; idx < MT * D_; idx += 256) {
            int m = idx & 31, d = idx >> 5;
            xs[m * 97 + d] = xb[d * N_ + m0 + m];
        }
        __syncthreads();  // B: tiles staged

        // Hot loop: this warp's a-half, both n of the pair per g2 quad.
        float z0 = 0.f, z1 = 0.f, z2 = 0.f, z3 = 0.f;
#pragma unroll 2
        for (int a = a0; a < a0 + 128; a += 4) {
            float4 q0 = *reinterpret_cast<const float4*>(g1p0 + a);
            float4 q1 = *reinterpret_cast<const float4*>(g1p1 + a);
            float4 g2 = *reinterpret_cast<const float4*>(g2l + a);
            float4 wv = *reinterpret_cast<const float4*>(c_ws + a);
            z0 = fmaf(fast_tanh(q0.x + g2.x), wv.x, z0);
            z1 = fmaf(fast_tanh(q0.y + g2.y), wv.y, z1);
            z2 = fmaf(fast_tanh(q1.x + g2.x), wv.x, z2);
            z3 = fmaf(fast_tanh(q1.y + g2.y), wv.y, z3);
            z0 = fmaf(fast_tanh(q0.z + g2.z), wv.z, z0);
            z1 = fmaf(fast_tanh(q0.w + g2.w), wv.w, z1);
            z2 = fmaf(fast_tanh(q1.z + g2.z), wv.z, z2);
            z3 = fmaf(fast_tanh(q1.w + g2.w), wv.w, z3);
        }
        float za = z0 + z1;   // partial for n = 2p
        float zb = z2 + z3;   // partial for n = 2p+1

        if (g == 1) {
            zbuf[(p << 1) * 32 + l]       = za;
            zbuf[((p << 1) + 1) * 32 + l] = zb;
        }
        __syncthreads();  // C: partials visible

        if (g == 0) {
            za += zbuf[(p << 1) * 32 + l];
            zb += zbuf[((p << 1) + 1) * 32 + l];
            att_s[(p << 1) * 33 + l]       = 1.0f / (1.0f + __expf(-(za + bias)));
            att_s[((p << 1) + 1) * 33 + l] = 1.0f / (1.0f + __expf(-(zb + bias)));
        }
        __syncthreads();  // D: att visible

        // Epilogue: group g covers m in [16g, 16g+16); paired n shares xs loads.
#pragma unroll 4
        for (int mm = 0; mm < 16; mm++) {
            int mli = (g << 4) + mm;
            float av0 = ar0[mli];
            float av1 = ar0[33 + mli];
            const float* xr = xs + mli * 97;
            float x0 = xr[l];
            float x1 = xr[l + 32];
            float x2 = xr[l + 64];
            o00 = fmaf(av0, x0, o00);
            o01 = fmaf(av0, x1, o01);
            o02 = fmaf(av0, x2, o02);
            o10 = fmaf(av1, x0, o10);
            o11 = fmaf(av1, x1, o11);
            o12 = fmaf(av1, x2, o12);
        }
    }

    // Combine m-halves and the two a-split warps per pair (atomics).
    float* op0 = out + (b * N_ + n0 + (p << 1)) * D_;
    float* op1 = op0 + D_;
    atomicAdd(op0 + l,      o00);
    atomicAdd(op0 + l + 32, o01);
    atomicAdd(op0 + l + 64, o02);
    atomicAdd(op1 + l,      o10);
    atomicAdd(op1 + l + 32, o11);
    atomicAdd(op1 + l + 64, o12);
}

// ---------------------------------------------------------------------------
extern "C" void kernel_launch(void* const* d_in, const int* in_sizes, int n_in,
                              void* d_out, int out_size) {
    const float* x    = (const float*)d_in[0];
    const float* Wg1  = (const float*)d_in[1];
    const float* Wg2  = (const float*)d_in[2];
    const float* bg   = (const float*)d_in[3];
    const float* Wa_w = (const float*)d_in[4];
    const float* Wa_b = (const float*)d_in[5];
    const float* ba   = (const float*)d_in[6];
    float* out = (float*)d_out;

    // out receives atomicAdd partials: zero it first.
    cudaMemsetAsync(d_out, 0, (size_t)out_size * sizeof(float));

    // Attention weights -> constant memory (async D2D, graph-capturable).
    cudaMemcpyToSymbolAsync(c_ws, Wa_w, ATTN_ * sizeof(float), 0,
                            cudaMemcpyDeviceToDevice);

    int proj_smem = (2 * 256 * 97 + D_ * PR) * (int)sizeof(float);
    cudaFuncSetAttribute(proj_kernel,
                         cudaFuncAttributeMaxDynamicSharedMemorySize, proj_smem);
    proj_kernel<<<(B_ * N_) / PR, 256, proj_smem>>>(x, Wg1, Wg2, bg);

    int attn_smem = SMEM_FLOATS * (int)sizeof(float);  // 55,968 B
    cudaFuncSetAttribute(attn_kernel,
                         cudaFuncAttributeMaxDynamicSharedMemorySize, attn_smem);
    attn_kernel<<<B_ * (N_ / NT) * 2, 256, attn_smem>>>(x, Wa_b, ba, out);
}

// round 13
// speedup vs baseline: 2.2345x; 1.0377x over previous
#include <cuda_runtime.h>
#include <cuda_fp16.h>

#define B_    4
#define D_    96
#define N_    512
#define ATTN_ 256

// Scratch (device globals: no allocation in kernel_launch)
__device__ __half  g_G1h[B_ * N_ * ATTN_];   // [b][n][a]
__device__ __half  g_G2h[B_ * N_ * ATTN_];   // [b][m][a] (bg folded in)
__device__ __half2 g_wsh[ATTN_ / 2];         // packed Wa_w (written by proj blk 0)
__constant__ __half2 c_wsh[ATTN_ / 2];       // uniform-port reads, zero crossbar

union HU { unsigned u; __half2 h; };
__device__ __forceinline__ __half2 U2H(unsigned u) { HU t; t.u = u; return t.h; }
__device__ __forceinline__ unsigned H2U(__half2 h) { HU t; t.h = h; return t.u; }

__device__ __forceinline__ __half2 tanh2(__half2 x) {
    unsigned y;
    asm("tanh.approx.f16x2 %0, %1;" : "=r"(y) : "r"(H2U(x)));
    return U2H(y);
}

// ---------------------------------------------------------------------------
// Kernel 1: projections -> half outputs. grid = B*N/8 = 256 blocks, 256 thr.
// Block 0 additionally packs Wa_w into g_wsh (half2).
// ---------------------------------------------------------------------------
#define PR 8

__global__ __launch_bounds__(256) void proj_kernel(
        const float* __restrict__ x,
        const float* __restrict__ Wg1,
        const float* __restrict__ Wg2,
        const float* __restrict__ bg,
        const float* __restrict__ Wa_w) {
    extern __shared__ float psm[];
    float* W1s = psm;                     // [256][97]
    float* W2s = psm + 256 * 97;          // [256][97]
    float* xs  = psm + 2 * 256 * 97;      // [96][8]

    int blk = blockIdx.x;
    int b   = blk >> 6;
    int n0  = (blk & 63) << 3;
    int tid = threadIdx.x;

    if (blk == 0 && tid < ATTN_ / 2)
        g_wsh[tid] = __floats2half2_rn(Wa_w[2 * tid], Wa_w[2 * tid + 1]);

    for (int idx = tid; idx < 256 * 24; idx += 256) {
        int a = idx / 24;
        int c = idx - a * 24;
        float4 v1 = reinterpret_cast<const float4*>(Wg1)[idx];
        float4 v2 = reinterpret_cast<const float4*>(Wg2)[idx];
        float* d1 = W1s + a * 97 + c * 4;
        float* d2 = W2s + a * 97 + c * 4;
        d1[0] = v1.x; d1[1] = v1.y; d1[2] = v1.z; d1[3] = v1.w;
        d2[0] = v2.x; d2[1] = v2.y; d2[2] = v2.z; d2[3] = v2.w;
    }

    const float* xb = x + b * D_ * N_;
    for (int idx = tid; idx < D_ * PR; idx += 256) {
        int d = idx >> 3, j = idx & 7;
        xs[idx] = xb[d * N_ + n0 + j];
    }
    __syncthreads();

    int a = tid;
    float acc1[PR], acc2[PR];
#pragma unroll
    for (int j = 0; j < PR; j++) { acc1[j] = 0.f; acc2[j] = 0.f; }

    const float* w1 = W1s + a * 97;
    const float* w2 = W2s + a * 97;
#pragma unroll 4
    for (int d = 0; d < D_; d++) {
        float wa = w1[d];
        float wb = w2[d];
        float4 x0 = *reinterpret_cast<const float4*>(xs + d * 8);
        float4 x1 = *reinterpret_cast<const float4*>(xs + d * 8 + 4);
        acc1[0] = fmaf(x0.x, wa, acc1[0]); acc2[0] = fmaf(x0.x, wb, acc2[0]);
        acc1[1] = fmaf(x0.y, wa, acc1[1]); acc2[1] = fmaf(x0.y, wb, acc2[1]);
        acc1[2] = fmaf(x0.z, wa, acc1[2]); acc2[2] = fmaf(x0.z, wb, acc2[2]);
        acc1[3] = fmaf(x0.w, wa, acc1[3]); acc2[3] = fmaf(x0.w, wb, acc2[3]);
        acc1[4] = fmaf(x1.x, wa, acc1[4]); acc2[4] = fmaf(x1.x, wb, acc2[4]);
        acc1[5] = fmaf(x1.y, wa, acc1[5]); acc2[5] = fmaf(x1.y, wb, acc2[5]);
        acc1[6] = fmaf(x1.z, wa, acc1[6]); acc2[6] = fmaf(x1.z, wb, acc2[6]);
        acc1[7] = fmaf(x1.w, wa, acc1[7]); acc2[7] = fmaf(x1.w, wb, acc2[7]);
    }

    float bgv = bg[a];
#pragma unroll
    for (int j = 0; j < PR; j++) {
        int row = b * N_ + n0 + j;
        g_G1h[row * ATTN_ + a] = __float2half_rn(acc1[j]);
        g_G2h[row * ATTN_ + a] = __float2half_rn(acc2[j] + bgv);
    }
}

// ---------------------------------------------------------------------------
// Kernel 2: fused pairwise tanh (f16x2) + sigmoid + output matmul.
// grid = B * 64 * 2 = 512 blocks, 256 threads (8 warps).
// Warp w: n-pair p = w&3, a-half g = w>>2. Lane l <-> m (32-m tile).
// Hot loop: half2 datapath, one MUFU per 2 tanh; weights via const port;
// 4 half2 accumulators flushed to fp32 every 32 a (bounds f16 round-off).
// ---------------------------------------------------------------------------
#define NT 8
#define MT 32

// byte offsets into dynamic smem
#define OFFB_G1H  0                     // 8*256*2  = 4096
#define OFFB_ATT  4096                  // 8*33*4   = 1056
#define OFFB_ZB   5152                  // 8*32*4   = 1024
#define OFFB_G2H  6176                  // 32*264*2 = 16896
#define OFFB_XS   23072                 // 32*97*4  = 12416
#define SMEM_BYTES 35488

#define KSTEP(Av, Bvv, Cv, Wv, A0, A1) {                     \
    __half2 g2h = U2H(Cv);                                   \
    __half2 w2  = U2H(Wv);                                   \
    __half2 t0  = tanh2(__hadd2(U2H(Av),  g2h));             \
    __half2 t1  = tanh2(__hadd2(U2H(Bvv), g2h));             \
    A0 = __hfma2(t0, w2, A0);                                \
    A1 = __hfma2(t1, w2, A1); }

__global__ __launch_bounds__(256, 4) void attn_kernel(
        const float* __restrict__ x,
        const float* __restrict__ Wa_b,
        const float* __restrict__ ba,
        float* __restrict__ out) {
    extern __shared__ char smc[];
    __half* G1s   = reinterpret_cast<__half*>(smc + OFFB_G1H);   // [n][256]
    float*  att_s = reinterpret_cast<float*>(smc + OFFB_ATT);    // [n][33]
    float*  zbuf  = reinterpret_cast<float*>(smc + OFFB_ZB);     // [n][32]
    __half* G2s   = reinterpret_cast<__half*>(smc + OFFB_G2H);   // [m][264]
    float*  xs    = reinterpret_cast<float*>(smc + OFFB_XS);     // [m][97]

    int blk  = blockIdx.x;         // 512 = B * 64 * 2
    int b    = blk >> 7;
    int r    = blk & 127;
    int n0   = (r >> 1) << 3;
    int mbase = (r & 1) << 8;
    int tid  = threadIdx.x;
    int w    = tid >> 5, l = tid & 31;
    int p    = w & 3;              // n-pair 0..3
    int g    = w >> 2;             // a-half 0/1

    // G1 tile: 8*256 halves = 4096 B = 256 uint4, one per thread.
    {
        const uint4* src = reinterpret_cast<const uint4*>(
                               g_G1h + (b * N_ + n0) * ATTN_);
        reinterpret_cast<uint4*>(smc + OFFB_G1H)[tid] = src[tid];
    }
    float bias = Wa_b[0] + ba[0];

    const float* xb = x + b * D_ * N_;
    float o00 = 0.f, o01 = 0.f, o02 = 0.f;
    float o10 = 0.f, o11 = 0.f, o12 = 0.f;

    const __half* g1r0 = G1s + (p << 1) * ATTN_;
    const __half* g1r1 = g1r0 + ATTN_;
    const __half* g2l  = G2s + l * 264;
    const float*  ar0  = att_s + (p << 1) * 33;
    const uint4*  wq   = reinterpret_cast<const uint4*>(c_wsh);

    for (int mt = 0; mt < 8; mt++) {
        int m0 = mbase + mt * MT;
        __syncthreads();  // A: prev tile's epilogue readers done

        // Stage G2 tile [m][264] halves (rows 528B = 33x16B, conflict-free)
        {
            const uint4* g2g = reinterpret_cast<const uint4*>(
                                   g_G2h + (b * N_ + m0) * ATTN_);
            for (int idx = tid; idx < 1024; idx += 256) {
                int m = idx >> 5, c = idx & 31;
                *(reinterpret_cast<uint4*>(G2s + m * 264) + c) = g2g[idx];
            }
        }
        // x tile [m][97] f32
        for (int idx = tid; idx < MT * D_; idx += 256) {
            int m = idx & 31, d = idx >> 5;
            xs[m * 97 + d] = xb[d * N_ + m0 + m];
        }
        __syncthreads();  // B: tiles staged

        // Hot loop: this warp's 128-a half, both n of the pair, half2 math.
        float zf0 = 0.f, zf1 = 0.f;
#pragma unroll 1
        for (int c = 0; c < 4; c++) {
            int ah = (g << 7) + (c << 5);            // half-index base, 32 a
            __half2 acc00 = __float2half2_rn(0.f), acc01 = acc00;
            __half2 acc10 = acc00, acc11 = acc00;
#pragma unroll
            for (int s = 0; s < 4; s++) {
                int off = ah + (s << 3);             // 8 a
                uint4 A  = *reinterpret_cast<const uint4*>(g1r0 + off);
                uint4 Bv = *reinterpret_cast<const uint4*>(g1r1 + off);
                uint4 C  = *reinterpret_cast<const uint4*>(g2l + off);
                uint4 W  = wq[off >> 3];             // const port
                KSTEP(A.x, Bv.x, C.x, W.x, acc00, acc10);
                KSTEP(A.y, Bv.y, C.y, W.y, acc01, acc11);
                KSTEP(A.z, Bv.z, C.z, W.z, acc00, acc10);
                KSTEP(A.w, Bv.w, C.w, W.w, acc01, acc11);
            }
            // Flush to fp32 (bounds f16 accumulation error)
            float2 f;
            f = __half22float2(acc00); zf0 += f.x + f.y;
            f = __half22float2(acc01); zf0 += f.x + f.y;
            f = __half22float2(acc10); zf1 += f.x + f.y;
            f = __half22float2(acc11); zf1 += f.x + f.y;
        }

        if (g == 1) {
            zbuf[(p << 1) * 32 + l]       = zf0;
            zbuf[((p << 1) + 1) * 32 + l] = zf1;
        }
        __syncthreads();  // C: partials visible

        if (g == 0) {
            zf0 += zbuf[(p << 1) * 32 + l];
            zf1 += zbuf[((p << 1) + 1) * 32 + l];
            att_s[(p << 1) * 33 + l]       = 1.0f / (1.0f + __expf(-(zf0 + bias)));
            att_s[((p << 1) + 1) * 33 + l] = 1.0f / (1.0f + __expf(-(zf1 + bias)));
        }
        __syncthreads();  // D: att visible

        // Epilogue: group g covers m in [16g,16g+16); paired n shares xs loads.
#pragma unroll 4
        for (int mm = 0; mm < 16; mm++) {
            int mli = (g << 4) + mm;
            float av0 = ar0[mli];
            float av1 = ar0[33 + mli];
            const float* xr = xs + mli * 97;
            float x0 = xr[l];
            float x1 = xr[l + 32];
            float x2 = xr[l + 64];
            o00 = fmaf(av0, x0, o00);
            o01 = fmaf(av0, x1, o01);
            o02 = fmaf(av0, x2, o02);
            o10 = fmaf(av1, x0, o10);
            o11 = fmaf(av1, x1, o11);
            o12 = fmaf(av1, x2, o12);
        }
    }

    // Combine m-halves and a-split warps (atomics into pre-zeroed out).
    float* op0 = out + (b * N_ + n0 + (p << 1)) * D_;
    float* op1 = op0 + D_;
    atomicAdd(op0 + l,      o00);
    atomicAdd(op0 + l + 32, o01);
    atomicAdd(op0 + l + 64, o02);
    atomicAdd(op1 + l,      o10);
    atomicAdd(op1 + l + 32, o11);
    atomicAdd(op1 + l + 64, o12);
}

// ---------------------------------------------------------------------------
extern "C" void kernel_launch(void* const* d_in, const int* in_sizes, int n_in,
                              void* d_out, int out_size) {
    const float* x    = (const float*)d_in[0];
    const float* Wg1  = (const float*)d_in[1];
    const float* Wg2  = (const float*)d_in[2];
    const float* bg   = (const float*)d_in[3];
    const float* Wa_w = (const float*)d_in[4];
    const float* Wa_b = (const float*)d_in[5];
    const float* ba   = (const float*)d_in[6];
    float* out = (float*)d_out;

    // out receives atomicAdd partials: zero it first.
    cudaMemsetAsync(d_out, 0, (size_t)out_size * sizeof(float));

    int proj_smem = (2 * 256 * 97 + D_ * PR) * (int)sizeof(float);
    cudaFuncSetAttribute(proj_kernel,
                         cudaFuncAttributeMaxDynamicSharedMemorySize, proj_smem);
    proj_kernel<<<(B_ * N_) / PR, 256, proj_smem>>>(x, Wg1, Wg2, bg, Wa_w);

    // Packed half2 weights -> constant memory (in-stream after proj; D2D).
    void* wsp = nullptr;
    cudaGetSymbolAddress(&wsp, g_wsh);
    cudaMemcpyToSymbolAsync(c_wsh, wsp, (ATTN_ / 2) * sizeof(__half2), 0,
                            cudaMemcpyDeviceToDevice);

    attn_kernel<<<B_ * (N_ / NT) * 2, 256, SMEM_BYTES>>>(x, Wa_b, ba, out);
}